// round 16
// baseline (speedup 1.0000x reference)
#include <cuda_runtime.h>
#include <math.h>
#include <stdint.h>

#define T_LEN 131072
#define NS 64
#define MD 8
#define NWARP 1184        // 2 warps/SMSP, one wave (8 warps/SM * 148)
#define NCH (16 * NWARP)  // 18944 chunks, 16 per warp
#define NSPLIT 17407      // chunks [0,17407) L=7, rest L=6 ; 17407*7+1537*6=131071
#define BURN 12
#define LMAX 7
#define ROUNDS (BURN + LMAX + 1)   // 20
#define NMLP (T_LEN / 8)

// ---- static device scratch ----
__device__ uint32_t g_w2[(size_t)T_LEN * 32];  // bf16x2 weights, fragment-packed
__device__ float g_mlpart[NMLP];
__device__ float g_S1[NCH];
__device__ unsigned int g_cnt = 0;

__device__ __forceinline__ int chunk_t0(int c) {
    return (c < NSPLIT) ? 1 + 7 * c : 1 + 7 * NSPLIT + 6 * (c - NSPLIT);
}
__device__ __forceinline__ int chunk_len(int c) { return (c < NSPLIT) ? 7 : 6; }

#define CVT_BF2(r, lo, hi) asm("cvt.rn.bf16x2.f32 %0, %1, %2;" : "=r"(r) : "f"(hi), "f"(lo))
#define HMUL2(r, a, b) asm("mul.bf16x2 %0, %1, %2;" : "=r"(r) : "r"(a), "r"(b))
#define MMA_BF16(d, a, b0, b1) \
    asm volatile("mma.sync.aligned.m16n8k16.row.col.f32.bf16.bf16.f32 " \
                 "{%0,%1,%2,%3}, {%4,%5,%6,%7}, {%8,%9}, {%0,%1,%2,%3};" \
                 : "+f"((d)[0]), "+f"((d)[1]), "+f"((d)[2]), "+f"((d)[3]) \
                 : "r"((a)[0]), "r"((a)[1]), "r"((a)[2]), "r"((a)[3]), "r"(b0), "r"(b1))

// word index for state-pair u=(j/2): thread lp=u&3 reads words [lp*8, lp*8+8)
__device__ __forceinline__ int sidx(int u) {
    return (u & 3) * 8 + (u >> 3) * 2 + ((u >> 2) & 1);
}

// ============================================================
// Pass 0: bf16x2 fragment-packed weights + per-block (maxlog - lgamma).
// One warp per t; lane u computes states 2u, 2u+1.
// ============================================================
__global__ void __launch_bounds__(256) pass0_kernel(const int* __restrict__ x,
                                                    const float* __restrict__ lambdas) {
    __shared__ float sll[NS * MD];
    __shared__ float slam[NS];
    __shared__ float slg[32];
    __shared__ float sml[8];
    int tid = threadIdx.x;
    for (int idx = tid; idx < NS * MD; idx += 256) sll[idx] = __logf(lambdas[idx]);
    if (tid < NS) {
        float s = 0.f;
        #pragma unroll
        for (int m = 0; m < MD; m++) s += lambdas[tid * MD + m];
        slam[tid] = s;
    }
    if (tid < 32) slg[tid] = lgammaf((float)tid + 1.0f);
    __syncthreads();

    int warp = tid >> 5, lane = tid & 31;
    int t = blockIdx.x * 8 + warp;

    int4 xa = *(const int4*)&x[(size_t)t * MD];
    int4 xb = *(const int4*)&x[(size_t)t * MD + 4];
    int xv[8] = {xa.x, xa.y, xa.z, xa.w, xb.x, xb.y, xb.z, xb.w};

    int j0 = 2 * lane, j1 = 2 * lane + 1;
    float e0 = -slam[j0], e1 = -slam[j1];
    #pragma unroll
    for (int m = 0; m < 8; m++) {
        float xm = (float)xv[m];
        e0 = fmaf(xm, sll[j0 * MD + m], e0);
        e1 = fmaf(xm, sll[j1 * MD + m], e1);
    }
    float mx = fmaxf(e0, e1);
    #pragma unroll
    for (int o = 16; o > 0; o >>= 1)
        mx = fmaxf(mx, __shfl_xor_sync(0xffffffffu, mx, o));
    uint32_t w2;
    CVT_BF2(w2, __expf(e0 - mx), __expf(e1 - mx));
    g_w2[(size_t)t * 32 + sidx(lane)] = w2;
    if (lane == 0) {
        float lg = 0.f;
        #pragma unroll
        for (int m = 0; m < 8; m++) lg += slg[xv[m] & 31];
        sml[warp] = (t == 0) ? 0.f : (mx - lg);
    }
    __syncthreads();
    if (tid == 0) {
        float s = 0.f;
        #pragma unroll
        for (int q = 0; q < 8; q++) s += sml[q];
        g_mlpart[blockIdx.x] = s;
    }
}

// ============================================================
// Pass 1: tensor-core batched scan. 2 warps/block, 592 blocks (2 warps
// per SMSP). Warp = 16 chunks (rows of V 16x64). D = V @ A^T per round,
// register repack with bf16x2 weight multiply, lag-1 norms, telescoped
// accounting. Last-arriving warp reduces everything -> out.
// ============================================================
__global__ void __launch_bounds__(64) pass1_tc(const int* __restrict__ x,
                                               const float* __restrict__ priors,
                                               const float* __restrict__ lambdas,
                                               const float* __restrict__ log_transition,
                                               float* __restrict__ out) {
    int tid = threadIdx.x;
    int lane = tid & 31;
    int gwarp = blockIdx.x * 2 + (tid >> 5);
    int quad = lane >> 2, lp = lane & 3;
    int cb = gwarp * 16;
    int c_lo = cb + quad, c_hi = cb + quad + 8;
    int t0_lo = chunk_t0(c_lo), L_lo = chunk_len(c_lo);
    int t0_hi = chunk_t0(c_hi), L_hi = chunk_len(c_hi);
    bool acc = (lp == 0);
    bool chunk0 = (gwarp == 0 && quad == 0);

    // B fragments = exp(log A)
    uint32_t bfr[4][8][2];
    #pragma unroll
    for (int kt = 0; kt < 4; kt++)
        #pragma unroll
        for (int nt = 0; nt < 8; nt++) {
            const float* ar = &log_transition[(nt * 8 + quad) * NS + kt * 16 + lp * 2];
            CVT_BF2(bfr[kt][nt][0], __expf(ar[0]), __expf(ar[1]));
            CVT_BF2(bfr[kt][nt][1], __expf(ar[8]), __expf(ar[9]));
        }

    uint32_t vfr[4][4];
    #pragma unroll
    for (int kt = 0; kt < 4; kt++)
        #pragma unroll
        for (int e = 0; e < 4; e++) vfr[kt][e] = 0x3F803F80u;

    uint32_t wcur[16], wnxt[16];   // [0..7] lo row words, [8..15] hi row words
    {
        int tl = min(max(t0_lo - BURN, 1), T_LEN - 1);
        int th = min(max(t0_hi - BURN, 1), T_LEN - 1);
        const uint4* pl = (const uint4*)&g_w2[(size_t)tl * 32 + lp * 8];
        const uint4* ph = (const uint4*)&g_w2[(size_t)th * 32 + lp * 8];
        uint4 a = __ldg(&pl[0]), b = __ldg(&pl[1]);
        wcur[0] = a.x; wcur[1] = a.y; wcur[2] = a.z; wcur[3] = a.w;
        wcur[4] = b.x; wcur[5] = b.y; wcur[6] = b.z; wcur[7] = b.w;
        uint4 cc = __ldg(&ph[0]), dd = __ldg(&ph[1]);
        wcur[8] = cc.x; wcur[9] = cc.y; wcur[10] = cc.z; wcur[11] = cc.w;
        wcur[12] = dd.x; wcur[13] = dd.y; wcur[14] = dd.z; wcur[15] = dd.w;
    }

    float s_prev_lo = 1.f, s_prev_hi = 1.f;
    float S_lo = 0.f, S_hi = 0.f;

    for (int q = 0; q < ROUNDS; q++) {
        if (q + 1 < ROUNDS) {
            int tl = min(max(t0_lo - BURN + q + 1, 1), T_LEN - 1);
            int th = min(max(t0_hi - BURN + q + 1, 1), T_LEN - 1);
            const uint4* pl = (const uint4*)&g_w2[(size_t)tl * 32 + lp * 8];
            const uint4* ph = (const uint4*)&g_w2[(size_t)th * 32 + lp * 8];
            uint4 a = __ldg(&pl[0]), b = __ldg(&pl[1]);
            wnxt[0] = a.x; wnxt[1] = a.y; wnxt[2] = a.z; wnxt[3] = a.w;
            wnxt[4] = b.x; wnxt[5] = b.y; wnxt[6] = b.z; wnxt[7] = b.w;
            uint4 cc = __ldg(&ph[0]), dd = __ldg(&ph[1]);
            wnxt[8] = cc.x; wnxt[9] = cc.y; wnxt[10] = cc.z; wnxt[11] = cc.w;
            wnxt[12] = dd.x; wnxt[13] = dd.y; wnxt[14] = dd.z; wnxt[15] = dd.w;
        }

        // chunk 0 exact init (replaces its burn vector just before t0's step)
        if (q == BURN && gwarp == 0) {
            float ev[16];
            #pragma unroll
            for (int kt = 0; kt < 4; kt++)
                #pragma unroll
                for (int u = 0; u < 4; u++) {
                    int j = kt * 16 + lp * 2 + ((u >> 1) << 3) + (u & 1);
                    float lam = 0.f, e = priors[j];
                    #pragma unroll
                    for (int m = 0; m < MD; m++) {
                        float l = lambdas[j * MD + m];
                        lam += l;
                        e = fmaf((float)x[m], __logf(l), e);
                    }
                    ev[kt * 4 + u] = e - lam;
                }
            float mx = ev[0];
            #pragma unroll
            for (int u = 1; u < 16; u++) mx = fmaxf(mx, ev[u]);
            mx = fmaxf(mx, __shfl_xor_sync(0xffffffffu, mx, 1));
            mx = fmaxf(mx, __shfl_xor_sync(0xffffffffu, mx, 2));
            if (quad == 0) {
                #pragma unroll
                for (int kt = 0; kt < 4; kt++) {
                    CVT_BF2(vfr[kt][0], __expf(ev[kt * 4 + 0] - mx), __expf(ev[kt * 4 + 1] - mx));
                    CVT_BF2(vfr[kt][2], __expf(ev[kt * 4 + 2] - mx), __expf(ev[kt * 4 + 3] - mx));
                }
                if (lane == 0) {
                    float lg0 = 0.f;
                    #pragma unroll
                    for (int m = 0; m < 8; m++) lg0 += lgammaf((float)x[m] + 1.0f);
                    S_lo = mx - lg0;
                }
            }
        }

        // D = V @ A^T
        float d[8][4];
        #pragma unroll
        for (int nt = 0; nt < 8; nt++)
            #pragma unroll
            for (int e = 0; e < 4; e++) d[nt][e] = 0.f;
        #pragma unroll
        for (int kt = 0; kt < 4; kt++)
            #pragma unroll
            for (int nt = 0; nt < 8; nt++)
                MMA_BF16(d[nt], vfr[kt], bfr[kt][nt][0], bfr[kt][nt][1]);

        // row-sums: ||v_{q-1}||_1 (A column-stochastic)
        float rl = 0.f, rh = 0.f;
        #pragma unroll
        for (int nt = 0; nt < 8; nt++) { rl += d[nt][0] + d[nt][1]; rh += d[nt][2] + d[nt][3]; }
        rl += __shfl_xor_sync(0xffffffffu, rl, 1);
        rl += __shfl_xor_sync(0xffffffffu, rl, 2);
        rh += __shfl_xor_sync(0xffffffffu, rh, 1);
        rh += __shfl_xor_sync(0xffffffffu, rh, 2);

        if (acc && q >= BURN) {
            if (q < BURN + L_lo) S_lo += __logf(s_prev_lo);
            if (q == BURN && !chunk0) S_lo -= __logf(rl);
            if (q == BURN + L_lo) S_lo += __logf(rl);
            if (q < BURN + L_hi) S_hi += __logf(s_prev_hi);
            if (q == BURN) S_hi -= __logf(rh);
            if (q == BURN + L_hi) S_hi += __logf(rh);
        }

        // scale by 1/s (float) then by w (bf16x2), repack D -> V frags
        float il = __frcp_rn(s_prev_lo), ih = __frcp_rn(s_prev_hi);
        #pragma unroll
        for (int kt = 0; kt < 4; kt++) {
            int n0 = 2 * kt, n1 = 2 * kt + 1;
            uint32_t p0, p1, p2, p3;
            CVT_BF2(p0, d[n0][0] * il, d[n0][1] * il);
            CVT_BF2(p1, d[n0][2] * ih, d[n0][3] * ih);
            CVT_BF2(p2, d[n1][0] * il, d[n1][1] * il);
            CVT_BF2(p3, d[n1][2] * ih, d[n1][3] * ih);
            HMUL2(vfr[kt][0], p0, wcur[2 * kt]);
            HMUL2(vfr[kt][1], p1, wcur[8 + 2 * kt]);
            HMUL2(vfr[kt][2], p2, wcur[2 * kt + 1]);
            HMUL2(vfr[kt][3], p3, wcur[8 + 2 * kt + 1]);
        }
        s_prev_lo = rl; s_prev_hi = rh;
        #pragma unroll
        for (int z = 0; z < 16; z++) wcur[z] = wnxt[z];
    }

    if (acc) { g_S1[c_lo] = S_lo; g_S1[c_hi] = S_hi; }

    // ---- last-warp final reduction ----
    __threadfence();
    unsigned int old = 0;
    if (lane == 0) old = atomicAdd(&g_cnt, 1u);
    old = __shfl_sync(0xffffffffu, old, 0);
    if (old == NWARP - 1) {
        float a0 = 0.f, a1 = 0.f, a2 = 0.f, a3 = 0.f;
        float a4 = 0.f, a5 = 0.f, a6 = 0.f, a7 = 0.f;
        // NCH = 18944 = 74*256 ; NMLP = 16384 = 64*256
        for (int k = lane * 8; k < NCH; k += 256) {
            float4 u = *(const float4*)&g_S1[k];
            float4 v = *(const float4*)&g_S1[k + 4];
            a0 += u.x; a1 += u.y; a2 += u.z; a3 += u.w;
            a4 += v.x; a5 += v.y; a6 += v.z; a7 += v.w;
        }
        for (int k = lane * 8; k < NMLP; k += 256) {
            float4 u = *(const float4*)&g_mlpart[k];
            float4 v = *(const float4*)&g_mlpart[k + 4];
            a0 += u.x; a1 += u.y; a2 += u.z; a3 += u.w;
            a4 += v.x; a5 += v.y; a6 += v.z; a7 += v.w;
        }
        double tot = ((double)a0 + a1) + ((double)a2 + a3)
                   + ((double)a4 + a5) + ((double)a6 + a7);
        #pragma unroll
        for (int o = 16; o > 0; o >>= 1)
            tot += __shfl_xor_sync(0xffffffffu, tot, o);
        if (lane == 0) { out[0] = (float)tot; g_cnt = 0; }
    }
}

// ============================================================
extern "C" void kernel_launch(void* const* d_in, const int* in_sizes, int n_in,
                              void* d_out, int out_size) {
    const int*   x              = (const int*)d_in[0];
    const float* lambdas        = (const float*)d_in[1];
    const float* log_transition = (const float*)d_in[2];
    const float* priors         = (const float*)d_in[3];
    float* out = (float*)d_out;

    pass0_kernel<<<T_LEN / 8, 256>>>(x, lambdas);
    pass1_tc<<<NWARP / 2, 64>>>(x, priors, lambdas, log_transition, out);
}

// round 17
// speedup vs baseline: 1.6020x; 1.6020x over previous
#include <cuda_runtime.h>
#include <math.h>
#include <stdint.h>

#define T_LEN 131072
#define NS 64
#define MD 8
#define NWARP 1184        // pass1: 2 warps/SMSP, one wave (8 warps/SM * 148)
#define NCH (16 * NWARP)  // 18944 chunks, 16 per warp
#define NSPLIT 17407      // chunks [0,17407) L=7, rest L=6 ; 17407*7+1537*6=131071
#define BURN 12
#define LMAX 7
#define ROUNDS (BURN + LMAX + 1)   // 20
#define P0_WARPS 2368     // pass0: 1184 blocks x 2 warps
#define P0_TPW 56         // timesteps per warp (2368*56 = 132608 >= T_LEN)
#define NMLP P0_WARPS

// ---- static device scratch ----
__device__ uint32_t g_w2[(size_t)T_LEN * 32];  // bf16x2 weights, fragment-packed
__device__ float g_mlpart[NMLP];
__device__ float g_S1[NCH];
__device__ unsigned int g_cnt = 0;

__device__ __forceinline__ int chunk_t0(int c) {
    return (c < NSPLIT) ? 1 + 7 * c : 1 + 7 * NSPLIT + 6 * (c - NSPLIT);
}
__device__ __forceinline__ int chunk_len(int c) { return (c < NSPLIT) ? 7 : 6; }

#define CVT_BF2(r, lo, hi) asm("cvt.rn.bf16x2.f32 %0, %1, %2;" : "=r"(r) : "f"(hi), "f"(lo))
#define HMUL2(r, a, b) asm("mul.bf16x2 %0, %1, %2;" : "=r"(r) : "r"(a), "r"(b))
#define MMA_BF16(d, a, b0, b1) \
    asm volatile("mma.sync.aligned.m16n8k16.row.col.f32.bf16.bf16.f32 " \
                 "{%0,%1,%2,%3}, {%4,%5,%6,%7}, {%8,%9}, {%0,%1,%2,%3};" \
                 : "+f"((d)[0]), "+f"((d)[1]), "+f"((d)[2]), "+f"((d)[3]) \
                 : "r"((a)[0]), "r"((a)[1]), "r"((a)[2]), "r"((a)[3]), "r"(b0), "r"(b1))

// word index for state-pair u: pass1 thread lp=u&3 reads words [lp*8, lp*8+8)
__device__ __forceinline__ int sidx(int u) {
    return (u & 3) * 8 + (u >> 3) * 2 + ((u >> 2) & 1);
}

// ============================================================
// Pass 0 (register-resident): each warp loops over 56 timesteps; lane
// owns states (2*lane, 2*lane+1) with loglam/lamsum in REGISTERS (no
// shared memory -> no bank conflicts). x prefetched one step ahead.
// lgamma via register table + shfl.idx. Emits bf16x2 packed weights and
// per-warp (maxlog - lgamma) partial sums.
// ============================================================
__global__ void __launch_bounds__(64) pass0_kernel(const int* __restrict__ x,
                                                   const float* __restrict__ lambdas) {
    int tid = threadIdx.x, lane = tid & 31;
    int gwarp = blockIdx.x * 2 + (tid >> 5);
    int tstart = gwarp * P0_TPW;
    int tcount = min(P0_TPW, T_LEN - tstart);
    if (tcount <= 0) { if (lane == 0) g_mlpart[gwarp] = 0.f; return; }

    // per-lane loglam/lamsum registers (states 2*lane, 2*lane+1)
    int j0 = 2 * lane, j1 = 2 * lane + 1;
    float ll0[MD], ll1[MD], lam0 = 0.f, lam1 = 0.f;
    #pragma unroll
    for (int m = 0; m < MD; m++) {
        float a = __ldg(&lambdas[j0 * MD + m]);
        float b = __ldg(&lambdas[j1 * MD + m]);
        lam0 += a; lam1 += b;
        ll0[m] = __logf(a); ll1[m] = __logf(b);
    }
    // lgamma register table: lane v holds lgamma(v+1), v in [0,32)
    float lgv = lgammaf((float)lane + 1.0f);

    // prefetch first x row
    int4 xa = __ldg((const int4*)&x[(size_t)tstart * MD]);
    int4 xb = __ldg((const int4*)&x[(size_t)tstart * MD + 4]);

    float Sml = 0.f;
    for (int k = 0; k < tcount; k++) {
        int t = tstart + k;
        int xv[8] = {xa.x, xa.y, xa.z, xa.w, xb.x, xb.y, xb.z, xb.w};
        if (k + 1 < tcount) {   // prefetch next row
            xa = __ldg((const int4*)&x[(size_t)(t + 1) * MD]);
            xb = __ldg((const int4*)&x[(size_t)(t + 1) * MD + 4]);
        }

        float e0 = -lam0, e1 = -lam1;
        #pragma unroll
        for (int m = 0; m < 8; m++) {
            float xm = (float)xv[m];
            e0 = fmaf(xm, ll0[m], e0);
            e1 = fmaf(xm, ll1[m], e1);
        }
        float mx = fmaxf(e0, e1);
        #pragma unroll
        for (int o = 16; o > 0; o >>= 1)
            mx = fmaxf(mx, __shfl_xor_sync(0xffffffffu, mx, o));
        uint32_t w2;
        CVT_BF2(w2, __expf(e0 - mx), __expf(e1 - mx));
        g_w2[(size_t)t * 32 + sidx(lane)] = w2;

        if (t != 0) {   // t=0 handled exactly by chunk-0 init in pass1
            float lg = 0.f;
            #pragma unroll
            for (int m = 0; m < 8; m++)
                lg += __shfl_sync(0xffffffffu, lgv, xv[m] & 31);
            Sml += mx - lg;   // same value in every lane; lane 0's copy used
        }
    }
    if (lane == 0) g_mlpart[gwarp] = Sml;
}

// ============================================================
// Pass 1: tensor-core batched scan (unchanged from R16). 2 warps/block,
// 592 blocks. Warp = 16 chunks (rows of V 16x64). D = V @ A^T per round,
// register repack with bf16x2 weight multiply, lag-1 norms, telescoped
// accounting. Last-arriving warp reduces everything -> out.
// ============================================================
__global__ void __launch_bounds__(64) pass1_tc(const int* __restrict__ x,
                                               const float* __restrict__ priors,
                                               const float* __restrict__ lambdas,
                                               const float* __restrict__ log_transition,
                                               float* __restrict__ out) {
    int tid = threadIdx.x;
    int lane = tid & 31;
    int gwarp = blockIdx.x * 2 + (tid >> 5);
    int quad = lane >> 2, lp = lane & 3;
    int cb = gwarp * 16;
    int c_lo = cb + quad, c_hi = cb + quad + 8;
    int t0_lo = chunk_t0(c_lo), L_lo = chunk_len(c_lo);
    int t0_hi = chunk_t0(c_hi), L_hi = chunk_len(c_hi);
    bool acc = (lp == 0);
    bool chunk0 = (gwarp == 0 && quad == 0);

    // B fragments = exp(log A)
    uint32_t bfr[4][8][2];
    #pragma unroll
    for (int kt = 0; kt < 4; kt++)
        #pragma unroll
        for (int nt = 0; nt < 8; nt++) {
            const float* ar = &log_transition[(nt * 8 + quad) * NS + kt * 16 + lp * 2];
            CVT_BF2(bfr[kt][nt][0], __expf(ar[0]), __expf(ar[1]));
            CVT_BF2(bfr[kt][nt][1], __expf(ar[8]), __expf(ar[9]));
        }

    uint32_t vfr[4][4];
    #pragma unroll
    for (int kt = 0; kt < 4; kt++)
        #pragma unroll
        for (int e = 0; e < 4; e++) vfr[kt][e] = 0x3F803F80u;

    uint32_t wcur[16], wnxt[16];
    {
        int tl = min(max(t0_lo - BURN, 1), T_LEN - 1);
        int th = min(max(t0_hi - BURN, 1), T_LEN - 1);
        const uint4* pl = (const uint4*)&g_w2[(size_t)tl * 32 + lp * 8];
        const uint4* ph = (const uint4*)&g_w2[(size_t)th * 32 + lp * 8];
        uint4 a = __ldg(&pl[0]), b = __ldg(&pl[1]);
        wcur[0] = a.x; wcur[1] = a.y; wcur[2] = a.z; wcur[3] = a.w;
        wcur[4] = b.x; wcur[5] = b.y; wcur[6] = b.z; wcur[7] = b.w;
        uint4 cc = __ldg(&ph[0]), dd = __ldg(&ph[1]);
        wcur[8] = cc.x; wcur[9] = cc.y; wcur[10] = cc.z; wcur[11] = cc.w;
        wcur[12] = dd.x; wcur[13] = dd.y; wcur[14] = dd.z; wcur[15] = dd.w;
    }

    float s_prev_lo = 1.f, s_prev_hi = 1.f;
    float S_lo = 0.f, S_hi = 0.f;

    for (int q = 0; q < ROUNDS; q++) {
        if (q + 1 < ROUNDS) {
            int tl = min(max(t0_lo - BURN + q + 1, 1), T_LEN - 1);
            int th = min(max(t0_hi - BURN + q + 1, 1), T_LEN - 1);
            const uint4* pl = (const uint4*)&g_w2[(size_t)tl * 32 + lp * 8];
            const uint4* ph = (const uint4*)&g_w2[(size_t)th * 32 + lp * 8];
            uint4 a = __ldg(&pl[0]), b = __ldg(&pl[1]);
            wnxt[0] = a.x; wnxt[1] = a.y; wnxt[2] = a.z; wnxt[3] = a.w;
            wnxt[4] = b.x; wnxt[5] = b.y; wnxt[6] = b.z; wnxt[7] = b.w;
            uint4 cc = __ldg(&ph[0]), dd = __ldg(&ph[1]);
            wnxt[8] = cc.x; wnxt[9] = cc.y; wnxt[10] = cc.z; wnxt[11] = cc.w;
            wnxt[12] = dd.x; wnxt[13] = dd.y; wnxt[14] = dd.z; wnxt[15] = dd.w;
        }

        // chunk 0 exact init (replaces its burn vector just before t0's step)
        if (q == BURN && gwarp == 0) {
            float ev[16];
            #pragma unroll
            for (int kt = 0; kt < 4; kt++)
                #pragma unroll
                for (int u = 0; u < 4; u++) {
                    int j = kt * 16 + lp * 2 + ((u >> 1) << 3) + (u & 1);
                    float lam = 0.f, e = priors[j];
                    #pragma unroll
                    for (int m = 0; m < MD; m++) {
                        float l = lambdas[j * MD + m];
                        lam += l;
                        e = fmaf((float)x[m], __logf(l), e);
                    }
                    ev[kt * 4 + u] = e - lam;
                }
            float mx = ev[0];
            #pragma unroll
            for (int u = 1; u < 16; u++) mx = fmaxf(mx, ev[u]);
            mx = fmaxf(mx, __shfl_xor_sync(0xffffffffu, mx, 1));
            mx = fmaxf(mx, __shfl_xor_sync(0xffffffffu, mx, 2));
            if (quad == 0) {
                #pragma unroll
                for (int kt = 0; kt < 4; kt++) {
                    CVT_BF2(vfr[kt][0], __expf(ev[kt * 4 + 0] - mx), __expf(ev[kt * 4 + 1] - mx));
                    CVT_BF2(vfr[kt][2], __expf(ev[kt * 4 + 2] - mx), __expf(ev[kt * 4 + 3] - mx));
                }
                if (lane == 0) {
                    float lg0 = 0.f;
                    #pragma unroll
                    for (int m = 0; m < 8; m++) lg0 += lgammaf((float)x[m] + 1.0f);
                    S_lo = mx - lg0;
                }
            }
        }

        // D = V @ A^T
        float d[8][4];
        #pragma unroll
        for (int nt = 0; nt < 8; nt++)
            #pragma unroll
            for (int e = 0; e < 4; e++) d[nt][e] = 0.f;
        #pragma unroll
        for (int kt = 0; kt < 4; kt++)
            #pragma unroll
            for (int nt = 0; nt < 8; nt++)
                MMA_BF16(d[nt], vfr[kt], bfr[kt][nt][0], bfr[kt][nt][1]);

        // row-sums: ||v_{q-1}||_1 (A column-stochastic)
        float rl = 0.f, rh = 0.f;
        #pragma unroll
        for (int nt = 0; nt < 8; nt++) { rl += d[nt][0] + d[nt][1]; rh += d[nt][2] + d[nt][3]; }
        rl += __shfl_xor_sync(0xffffffffu, rl, 1);
        rl += __shfl_xor_sync(0xffffffffu, rl, 2);
        rh += __shfl_xor_sync(0xffffffffu, rh, 1);
        rh += __shfl_xor_sync(0xffffffffu, rh, 2);

        if (acc && q >= BURN) {
            if (q < BURN + L_lo) S_lo += __logf(s_prev_lo);
            if (q == BURN && !chunk0) S_lo -= __logf(rl);
            if (q == BURN + L_lo) S_lo += __logf(rl);
            if (q < BURN + L_hi) S_hi += __logf(s_prev_hi);
            if (q == BURN) S_hi -= __logf(rh);
            if (q == BURN + L_hi) S_hi += __logf(rh);
        }

        // scale by 1/s (float) then by w (bf16x2), repack D -> V frags
        float il = __frcp_rn(s_prev_lo), ih = __frcp_rn(s_prev_hi);
        #pragma unroll
        for (int kt = 0; kt < 4; kt++) {
            int n0 = 2 * kt, n1 = 2 * kt + 1;
            uint32_t p0, p1, p2, p3;
            CVT_BF2(p0, d[n0][0] * il, d[n0][1] * il);
            CVT_BF2(p1, d[n0][2] * ih, d[n0][3] * ih);
            CVT_BF2(p2, d[n1][0] * il, d[n1][1] * il);
            CVT_BF2(p3, d[n1][2] * ih, d[n1][3] * ih);
            HMUL2(vfr[kt][0], p0, wcur[2 * kt]);
            HMUL2(vfr[kt][1], p1, wcur[8 + 2 * kt]);
            HMUL2(vfr[kt][2], p2, wcur[2 * kt + 1]);
            HMUL2(vfr[kt][3], p3, wcur[8 + 2 * kt + 1]);
        }
        s_prev_lo = rl; s_prev_hi = rh;
        #pragma unroll
        for (int z = 0; z < 16; z++) wcur[z] = wnxt[z];
    }

    if (acc) { g_S1[c_lo] = S_lo; g_S1[c_hi] = S_hi; }

    // ---- last-warp final reduction ----
    __threadfence();
    unsigned int old = 0;
    if (lane == 0) old = atomicAdd(&g_cnt, 1u);
    old = __shfl_sync(0xffffffffu, old, 0);
    if (old == NWARP - 1) {
        float a0 = 0.f, a1 = 0.f, a2 = 0.f, a3 = 0.f;
        float a4 = 0.f, a5 = 0.f, a6 = 0.f, a7 = 0.f;
        // NCH = 18944 (mult of 8) ; NMLP = 2368 (mult of 8)
        for (int k = lane * 8; k < NCH; k += 256) {
            float4 u = *(const float4*)&g_S1[k];
            float4 v = *(const float4*)&g_S1[k + 4];
            a0 += u.x; a1 += u.y; a2 += u.z; a3 += u.w;
            a4 += v.x; a5 += v.y; a6 += v.z; a7 += v.w;
        }
        for (int k = lane * 8; k < NMLP; k += 256) {
            float4 u = *(const float4*)&g_mlpart[k];
            float4 v = *(const float4*)&g_mlpart[k + 4];
            a0 += u.x; a1 += u.y; a2 += u.z; a3 += u.w;
            a4 += v.x; a5 += v.y; a6 += v.z; a7 += v.w;
        }
        double tot = ((double)a0 + a1) + ((double)a2 + a3)
                   + ((double)a4 + a5) + ((double)a6 + a7);
        #pragma unroll
        for (int o = 16; o > 0; o >>= 1)
            tot += __shfl_xor_sync(0xffffffffu, tot, o);
        if (lane == 0) { out[0] = (float)tot; g_cnt = 0; }
    }
}

// ============================================================
extern "C" void kernel_launch(void* const* d_in, const int* in_sizes, int n_in,
                              void* d_out, int out_size) {
    const int*   x              = (const int*)d_in[0];
    const float* lambdas        = (const float*)d_in[1];
    const float* log_transition = (const float*)d_in[2];
    const float* priors         = (const float*)d_in[3];
    float* out = (float*)d_out;

    pass0_kernel<<<P0_WARPS / 2, 64>>>(x, lambdas);
    pass1_tc<<<NWARP / 2, 64>>>(x, priors, lambdas, log_transition, out);
}